// round 7
// baseline (speedup 1.0000x reference)
#include <cuda_runtime.h>
#include <cuda_bf16.h>
#include <math.h>

// FPQuantizer (fp8_e4m3 flex-bias fake-quant), 8192x8192 fp32. Pure streaming.
//
// Identity: clip(x, -rowabsmax, rowabsmax) == x (rowabsmax >= |x| by
// definition), so the reference's per-row reduction is dead code and the op
// is purely elementwise:
//
//   bias  = bf16(2^4 - log2(448) + log2(2 - 2^-4) - 1) = 7.15625 = 7 + 0.15625
//   ls    = floor(log2|x| + bias)
//         = (e-127) + 7 + [log2(m) + 0.15625 >= 1]      (x = m*2^(e-127), m in [1,2))
//         = (e-127) + 7 + [m >= 2^0.84375]              <-- R5 fix: threshold is
//                                                           2^0.84375 ~= 1.7948,
//                                                           NOT 2^-0.15625 (~0.897,
//                                                           which was always true)
//   ls    = max(ls, 1)
//   scale = 2^(ls - 5 - bias) = C * 2^(ls - 12),   C = 2^-0.15625
//   out   = rint(x / scale) * scale    (half-to-even, IEEE division)
//
// Zero/subnormal x: e==0 -> ls <= -119 -> clamped to 1; rint(tiny/scale)=0,
// matching the reference. Fully branchless per element.

__device__ __forceinline__ float fpq_one(float x, float C, float Cth,
                                         int lsBias, int sExpOff) {
    unsigned bits = __float_as_uint(x) & 0x7FFFFFFFu;
    int e = (int)(bits >> 23);
    // mantissa re-biased into [1,2); garbage when e==0 but ls clamps anyway
    float m = __uint_as_float((bits & 0x007FFFFFu) | 0x3F800000u);
    int ls = e + lsBias + (m >= Cth ? 1 : 0);
    ls = max(ls, 1);
    // scale = C * 2^(ls-12); biased exponent = ls + sExpOff (sExpOff = 127-12 = 115)
    float scale = __uint_as_float((unsigned)(ls + sExpOff) << 23) * C;
    // IEEE-rounded division (matches the reference's fp32 divide exactly at
    // half-integer rounding boundaries), then half-to-even round
    return rintf(__fdiv_rn(x, scale)) * scale;
}

__device__ __forceinline__ float4 fpq_vec4(float4 v, float C, float Cth,
                                           int lsBias, int sExpOff) {
    float4 r;
    r.x = fpq_one(v.x, C, Cth, lsBias, sExpOff);
    r.y = fpq_one(v.y, C, Cth, lsBias, sExpOff);
    r.z = fpq_one(v.z, C, Cth, lsBias, sExpOff);
    r.w = fpq_one(v.w, C, Cth, lsBias, sExpOff);
    return r;
}

// 2x float4 per thread (blocked within a block for coalescing), streaming
// cache hints (no reuse -> evict-first on both load and store paths).
__global__ void __launch_bounds__(256, 8)
FPQuantizer_76312978915927_kernel(const float4* __restrict__ in,
                                  float4* __restrict__ out,
                                  int n4, float C, float Cth,
                                  int lsBias, int sExpOff) {
    int base = blockIdx.x * (blockDim.x * 2) + threadIdx.x;
    int i0 = base;
    int i1 = base + blockDim.x;
    bool p0 = i0 < n4;
    bool p1 = i1 < n4;
    // Front-batch both loads for MLP before any compute.
    float4 v0, v1;
    if (p0) v0 = __ldcs(&in[i0]);
    if (p1) v1 = __ldcs(&in[i1]);
    if (p0) __stcs(&out[i0], fpq_vec4(v0, C, Cth, lsBias, sExpOff));
    if (p1) __stcs(&out[i1], fpq_vec4(v1, C, Cth, lsBias, sExpOff));
}

// Scalar tail (n not divisible by 4 -- defensive; 8192*8192 is divisible).
__global__ void FPQuantizer_tail_kernel(const float* __restrict__ in,
                                        float* __restrict__ out,
                                        int start, int n,
                                        float C, float Cth,
                                        int lsBias, int sExpOff) {
    int i = start + blockIdx.x * blockDim.x + threadIdx.x;
    if (i < n) out[i] = fpq_one(in[i], C, Cth, lsBias, sExpOff);
}

extern "C" void kernel_launch(void* const* d_in, const int* in_sizes, int n_in,
                              void* d_out, int out_size) {
    const float* x = (const float*)d_in[0];
    float* out = (float*)d_out;
    int n = in_sizes[0];

    // Host-side exact constant derivation (mirrors the reference formula,
    // including the bf16 cast of the bias).
    const double ebits = 4.0, mbits = 5.0, max_norm = 448.0;
    double biasd = pow(2.0, ebits) - log2(max_norm)
                 + log2(2.0 - pow(2.0, 1.0 - mbits)) - 1.0;          // 7.146841...
    float biasbf = __bfloat162float(__float2bfloat16((float)biasd)); // 7.15625
    int ibias = (int)floorf(biasbf);                                  // 7
    double frac = (double)biasbf - (double)ibias;                     // 0.15625
    float C   = (float)pow(2.0, -frac);        // 2^-0.15625: scale fractional factor
    float Cth = (float)pow(2.0, 1.0 - frac);   // 2^0.84375 ~= 1.794838: mantissa threshold
    int lsBias  = ibias - 127;                 // -120
    int sExpOff = 127 - (int)mbits - ibias;    // 115: biased-exponent offset (2^(ls-12))

    int n4 = n >> 2;
    if (n4 > 0) {
        const int threads = 256;
        const int per_block = threads * 2;  // 2 float4 per thread
        int blocks = (n4 + per_block - 1) / per_block;
        FPQuantizer_76312978915927_kernel<<<blocks, threads>>>(
            (const float4*)x, (float4*)out, n4, C, Cth, lsBias, sExpOff);
    }
    int tail_start = n4 << 2;
    int tail = n - tail_start;
    if (tail > 0) {
        FPQuantizer_tail_kernel<<<1, 128>>>(x, out, tail_start, n, C, Cth, lsBias, sExpOff);
    }
}

// round 13
// speedup vs baseline: 1.0123x; 1.0123x over previous
#include <cuda_runtime.h>
#include <cuda_bf16.h>
#include <math.h>

// FPQuantizer (fp8_e4m3 flex-bias fake-quant), 8192x8192 fp32. Pure streaming.
//
// Identity: clip(x, -rowabsmax, rowabsmax) == x, so the reference's per-row
// reduction is dead code and the op is purely elementwise:
//
//   bias  = bf16(2^4 - log2(448) + log2(2 - 2^-4) - 1) = 7.15625 = 7 + 0.15625
//   ls    = floor(log2|x| + bias) = (e-127) + 7 + [m >= 2^0.84375]
//   ls    = max(ls, 1)
//   scale = C * 2^(ls - 12),  C = 2^-0.15625   (exact: exponent shift of C)
//   out   = rint(x / scale) * scale
//
// Div -> mul: q = x * 2^(12-ls) * invC, with invC = fl(1/C).
//   - x * 2^(12-ls) is EXACT (power-of-two multiply)
//   - output side (q*C)*2^(ls-12) rounds bit-identically to q*scale_f, since
//     scale_f = C*2^(ls-12) is exact in fp32
//   - only q near half-integer boundaries can differ from the IEEE-div path:
//     q in [32,64), ulp 2^-18 -> O(100s) of 64M elements shift one step
//     -> ~4e-5 rel-err, 25x under threshold. Removes the ~9-instruction
//     __fdiv_rn MUFU sequence + FCHK branch per element.
//
// Zero/subnormal x: e==0 -> ls clamps to 1, q ~ 0, rint -> 0. Branchless.

__device__ __forceinline__ float fpq_one(float x, float C, float invC, float Cth,
                                         int lsBias) {
    unsigned bits = __float_as_uint(x) & 0x7FFFFFFFu;
    int e = (int)(bits >> 23);
    // mantissa re-biased into [1,2); garbage when e==0 but ls clamps anyway
    float m = __uint_as_float((bits & 0x007FFFFFu) | 0x3F800000u);
    int ls = e + lsBias + (m >= Cth ? 1 : 0);
    ls = max(ls, 1);
    float p2s  = __uint_as_float((unsigned)(ls + 115) << 23);  // 2^(ls-12), exact
    float p2i  = __uint_as_float((unsigned)(139 - ls) << 23);  // 2^(12-ls), exact
    float q = rintf((x * p2i) * invC);     // x*p2i exact; one rounding in *invC
    return (q * C) * p2s;                  // q*C rounds == q*scale_f; *p2s exact
}

__device__ __forceinline__ float4 fpq_vec4(float4 v, float C, float invC,
                                           float Cth, int lsBias) {
    float4 r;
    r.x = fpq_one(v.x, C, invC, Cth, lsBias);
    r.y = fpq_one(v.y, C, invC, Cth, lsBias);
    r.z = fpq_one(v.z, C, invC, Cth, lsBias);
    r.w = fpq_one(v.w, C, invC, Cth, lsBias);
    return r;
}

// 2x float4 per thread (blocked within a block for coalescing), streaming
// cache hints (no reuse -> evict-first on both load and store paths).
__global__ void __launch_bounds__(256, 8)
FPQuantizer_76312978915927_kernel(const float4* __restrict__ in,
                                  float4* __restrict__ out,
                                  int n4, float C, float invC, float Cth,
                                  int lsBias) {
    int base = blockIdx.x * (blockDim.x * 2) + threadIdx.x;
    int i0 = base;
    int i1 = base + blockDim.x;
    bool p0 = i0 < n4;
    bool p1 = i1 < n4;
    // Front-batch both loads for MLP before any compute.
    float4 v0, v1;
    if (p0) v0 = __ldcs(&in[i0]);
    if (p1) v1 = __ldcs(&in[i1]);
    if (p0) __stcs(&out[i0], fpq_vec4(v0, C, invC, Cth, lsBias));
    if (p1) __stcs(&out[i1], fpq_vec4(v1, C, invC, Cth, lsBias));
}

// Scalar tail (n not divisible by 4 -- defensive; 8192*8192 is divisible).
__global__ void FPQuantizer_tail_kernel(const float* __restrict__ in,
                                        float* __restrict__ out,
                                        int start, int n,
                                        float C, float invC, float Cth,
                                        int lsBias) {
    int i = start + blockIdx.x * blockDim.x + threadIdx.x;
    if (i < n) out[i] = fpq_one(in[i], C, invC, Cth, lsBias);
}

extern "C" void kernel_launch(void* const* d_in, const int* in_sizes, int n_in,
                              void* d_out, int out_size) {
    const float* x = (const float*)d_in[0];
    float* out = (float*)d_out;
    int n = in_sizes[0];

    // Host-side exact constant derivation (mirrors the reference formula,
    // including the bf16 cast of the bias).
    const double ebits = 4.0, mbits = 5.0, max_norm = 448.0;
    double biasd = pow(2.0, ebits) - log2(max_norm)
                 + log2(2.0 - pow(2.0, 1.0 - mbits)) - 1.0;          // 7.146841...
    float biasbf = __bfloat162float(__float2bfloat16((float)biasd)); // 7.15625
    int ibias = (int)floorf(biasbf);                                  // 7
    double frac = (double)biasbf - (double)ibias;                     // 0.15625
    float C    = (float)pow(2.0, -frac);        // 2^-0.15625: scale fractional factor
    float invC = (float)(1.0 / (double)C);      // closest float to 1/C_f
    float Cth  = (float)pow(2.0, 1.0 - frac);   // 2^0.84375 ~= 1.794838: mantissa threshold
    int lsBias = ibias - 127;                   // -120
    // exponent offsets 115 (= 127-12) and 139 (= 127+12) are inlined in-kernel;
    // 12 = mbits + ibias.

    int n4 = n >> 2;
    if (n4 > 0) {
        const int threads = 256;
        const int per_block = threads * 2;  // 2 float4 per thread
        int blocks = (n4 + per_block - 1) / per_block;
        FPQuantizer_76312978915927_kernel<<<blocks, threads>>>(
            (const float4*)x, (float4*)out, n4, C, invC, Cth, lsBias);
    }
    int tail_start = n4 << 2;
    int tail = n - tail_start;
    if (tail > 0) {
        FPQuantizer_tail_kernel<<<1, 128>>>(x, out, tail_start, n, C, invC, Cth, lsBias);
    }
}